// round 15
// baseline (speedup 1.0000x reference)
#include <cuda_runtime.h>
#include <cstdint>

#define T_STEPS 2048
#define BATCH   256
#define HDIM    200
#define IN_DIM  27
#define NCLS    2

#define NGROUPS  16     // batch tiles; groups are mutually independent
#define GSIZE    8      // hd tiles per group -> 8-CTA barrier groups
#define GRID_CTAS (NGROUPS * GSIZE)   // 128 CTAs, 1/SM (SMEM-limited)
#define TB 16     // batches per CTA
#define TH 25     // hidden units per CTA
#define ROWS 100  // 4 gates * TH
#define ROWS_PAD 128
#define NTHREADS 512    // 16 warps; K split 4 ways; 4x4 register tile per thread

// SMEM strides (floats): 16B-aligned rows, conflict-free quad-banks for LDS.128
#define WHH_S 212   // 53 quads/row, 53%8=5 -> 8 consecutive rows hit 8 banks
#define WIH_S 36    // 9 quads,  9%8=1
#define HS_S  204   // 51 quads, 51%8=3
#define XS_S  36
#define RED_S 17    // odd stride -> <=2-way on export/gather

struct SmemLayout {
    float whh[ROWS_PAD][WHH_S];      // 108544 B
    float wih[ROWS_PAD][WIH_S];      //  18432 B
    float hs[TB][HS_S];              //  13056 B (h staging, full HDIM per batch)
    float xs[2][TB][XS_S];           //   4608 B (double-buffered x)
    float bias[ROWS_PAD];            //    512 B
    float red[4][ROWS_PAD][RED_S];   //  34816 B (K-split partials, all 4 slices)
};
// total 179968 B -> 1 CTA/SM; 128 CTAs <= 148 SMs -> all co-resident.

__device__ float g_h[2][BATCH][HDIM];          // double-buffered h exchange (L2)
__device__ unsigned g_cnt[NGROUPS * 64];       // per-group arrive counters (monotonic)
__device__ unsigned g_ep [NGROUPS * 64];       // per-group epochs, 256B apart

typedef unsigned long long u64;

__device__ __forceinline__ void ffma2(u64& d, u64 a, u64 b) {
    asm("fma.rn.f32x2 %0, %1, %2, %3;" : "=l"(d) : "l"(a), "l"(b), "l"(d));
}
__device__ __forceinline__ float f2sum(u64 v) {
    return __uint_as_float((unsigned)v) + __uint_as_float((unsigned)(v >> 32));
}
__device__ __forceinline__ float sigf(float x) {
    float e = __expf(-x);
    return __fdividef(1.0f, 1.0f + e);
}
__device__ __forceinline__ float tanh_fast(float x) {
    float e = __expf(-2.0f * x);
    return __fdividef(2.0f, 1.0f + e) - 1.0f;
}
__device__ __forceinline__ unsigned ld_acq(const unsigned* p) {
    unsigned v;
    asm volatile("ld.acquire.gpu.u32 %0, [%1];" : "=r"(v) : "l"(p) : "memory");
    return v;
}
__device__ __forceinline__ unsigned atom_add_acqrel(unsigned* p, unsigned v) {
    unsigned o;
    asm volatile("atom.add.acq_rel.gpu.u32 %0, [%1], %2;"
                 : "=r"(o) : "l"(p), "r"(v) : "memory");
    return o;
}
__device__ __forceinline__ void bar_named128(int id) {  // 128-thread named barrier
    asm volatile("bar.sync %0, 128;" :: "r"(id) : "memory");
}

__global__ void __launch_bounds__(NTHREADS, 1)
lstm_persistent(const float* __restrict__ x,      // [B][T][27]
                const float* __restrict__ W_ih,   // [800][27]
                const float* __restrict__ W_hh,   // [800][200]
                const float* __restrict__ b_ih,   // [800]
                const float* __restrict__ b_hh,   // [800]
                const float* __restrict__ fc_w,   // [2][200]
                const float* __restrict__ fc_b,   // [2]
                float* __restrict__ out, int out_size)
{
    extern __shared__ float smem_f[];
    SmemLayout& s = *reinterpret_cast<SmemLayout*>(smem_f);

    const int tid = threadIdx.x;
    const int bt  = blockIdx.x >> 3;   // group id (batch tile)
    const int ht  = blockIdx.x & 7;    // hd tile within group
    const int b0  = bt * TB;
    const int hd0 = ht * TH;

    unsigned* cnt = &g_cnt[bt * 64];
    unsigned* ep  = &g_ep [bt * 64];

    // ---- one-time staging: weight slices (row r = gate*25 + hl), bias ----
    for (int i = tid; i < ROWS_PAD * HDIM; i += NTHREADS) {
        int r = i / HDIM, k = i - r * HDIM;
        float v = 0.0f;
        if (r < ROWS) {
            int gate = r / TH, hl = r - gate * TH;
            v = W_hh[(gate * HDIM + hd0 + hl) * HDIM + k];
        }
        s.whh[r][k] = v;
    }
    for (int i = tid; i < ROWS_PAD * 28; i += NTHREADS) {
        int r = i / 28, k = i - r * 28;
        float v = 0.0f;
        if (r < ROWS && k < IN_DIM) {
            int gate = r / TH, hl = r - gate * TH;
            v = W_ih[(gate * HDIM + hd0 + hl) * IN_DIM + k];
        }
        s.wih[r][k] = v;
    }
    if (tid < ROWS_PAD) {
        float v = 0.0f;
        if (tid < ROWS) {
            int gate = tid / TH, hl = tid - gate * TH;
            int gr = gate * HDIM + hd0 + hl;
            v = b_ih[gr] + b_hh[gr];
        }
        s.bias[tid] = v;
    }
    for (int i = tid; i < TB * 28; i += NTHREADS) { // xs[0] for t=0
        int bl = i / 28, k = i - bl * 28;
        s.xs[0][bl][k] = (k < IN_DIM)
            ? x[((size_t)(b0 + bl) * T_STEPS + 0) * IN_DIM + k] : 0.0f;
    }

    // Barrier bookkeeping: read epoch BEFORE first arrive (race-free; relative
    // compare -> replay/wrap safe).
    unsigned seen = 0;
    if (tid == 0) seen = ld_acq(ep);
    __syncthreads();

    // GEMM tile (K-split-4, gate-aligned): rows {jb, jb+25, jb+50, jb+75}
    // = gates {i,f,g,o} of hidden unit jb. Real rows only for jb < 25.
    const int ks = tid >> 7;          // 0..3
    const int p  = tid & 127;
    const int jb = p >> 2;            // 0..31 (25..31 = padding rows)
    const int bb = p & 3;
    const bool act = (jb < TH);
    const int r0g = jb, r1g = jb + 25, r2g = jb + 50, r3g = jb + 75;
    const int kq_lo = 14 * ks;        // h-quads: 14,14,14,8 (+x on ks3)

    // Cell tile: thread tid<400 owns item (batch cb, unit cu); c in register.
    const int cb = tid / TH;
    const int cu = tid - cb * TH;
    const bool c_act = (tid < TB * TH);
    float creg = 0.0f;
    float bsi = 0, bsf = 0, bsg = 0, bso = 0;
    if (c_act) {
        bsi = s.bias[cu];           bsf = s.bias[cu + TH];
        bsg = s.bias[cu + 2 * TH];  bso = s.bias[cu + 3 * TH];
    }

    // x prefetch coordinates (tid < 448 holds one padded x element)
    const int xp_bl = tid / 28;
    const int xp_k  = tid - xp_bl * 28;
    const bool xp_on = (tid < TB * 28);

    // 4x4 accumulator tile [gate][batch]
    u64 A00, A01, A02, A03, A10, A11, A12, A13;
    u64 A20, A21, A22, A23, A30, A31, A32, A33;

#define GEMM_QUAD(WARR, VARR, Q)                                               \
    {                                                                          \
        ulonglong2 W0 = *reinterpret_cast<const ulonglong2*>(&WARR[r0g][4*(Q)]);\
        ulonglong2 W1 = *reinterpret_cast<const ulonglong2*>(&WARR[r1g][4*(Q)]);\
        ulonglong2 W2 = *reinterpret_cast<const ulonglong2*>(&WARR[r2g][4*(Q)]);\
        ulonglong2 W3 = *reinterpret_cast<const ulonglong2*>(&WARR[r3g][4*(Q)]);\
        ulonglong2 V0 = *reinterpret_cast<const ulonglong2*>(&VARR[bb][4*(Q)]);\
        ulonglong2 V1 = *reinterpret_cast<const ulonglong2*>(&VARR[bb+4][4*(Q)]);\
        ulonglong2 V2 = *reinterpret_cast<const ulonglong2*>(&VARR[bb+8][4*(Q)]);\
        ulonglong2 V3 = *reinterpret_cast<const ulonglong2*>(&VARR[bb+12][4*(Q)]);\
        ffma2(A00,V0.x,W0.x); ffma2(A00,V0.y,W0.y);                            \
        ffma2(A01,V1.x,W0.x); ffma2(A01,V1.y,W0.y);                            \
        ffma2(A02,V2.x,W0.x); ffma2(A02,V2.y,W0.y);                            \
        ffma2(A03,V3.x,W0.x); ffma2(A03,V3.y,W0.y);                            \
        ffma2(A10,V0.x,W1.x); ffma2(A10,V0.y,W1.y);                            \
        ffma2(A11,V1.x,W1.x); ffma2(A11,V1.y,W1.y);                            \
        ffma2(A12,V2.x,W1.x); ffma2(A12,V2.y,W1.y);                            \
        ffma2(A13,V3.x,W1.x); ffma2(A13,V3.y,W1.y);                            \
        ffma2(A20,V0.x,W2.x); ffma2(A20,V0.y,W2.y);                            \
        ffma2(A21,V1.x,W2.x); ffma2(A21,V1.y,W2.y);                            \
        ffma2(A22,V2.x,W2.x); ffma2(A22,V2.y,W2.y);                            \
        ffma2(A23,V3.x,W2.x); ffma2(A23,V3.y,W2.y);                            \
        ffma2(A30,V0.x,W3.x); ffma2(A30,V0.y,W3.y);                            \
        ffma2(A31,V1.x,W3.x); ffma2(A31,V1.y,W3.y);                            \
        ffma2(A32,V2.x,W3.x); ffma2(A32,V2.y,W3.y);                            \
        ffma2(A33,V3.x,W3.x); ffma2(A33,V3.y,W3.y);                            \
    }

    // reset accumulators + (slice 3 only) x-part for buffer `buf`
    auto do_xpart = [&](int buf) {
        A00=A01=A02=A03=A10=A11=A12=A13=0ull;
        A20=A21=A22=A23=A30=A31=A32=A33=0ull;
        if (ks == 3) {
            #pragma unroll
            for (int q = 0; q < 7; ++q) GEMM_QUAD(s.wih, s.xs[buf], q);
        }
    };

    do_xpart(0);   // x-part for t=0 (xs[0] staged above, synced)

    for (int t = 0; t < T_STEPS; ++t) {
        // prefetch x(t+1): DRAM latency overlaps wait + staging + GEMM
        float xreg = 0.0f;
        if (t + 1 < T_STEPS && xp_on && xp_k < IN_DIM)
            xreg = __ldg(&x[((size_t)(b0 + xp_bl) * T_STEPS + (t + 1)) * IN_DIM + xp_k]);

        if (t > 0) {
            // ---- wait for peers' h(t-1) ----
            if (tid == 0) {
                unsigned v;
                do { v = ld_acq(ep); } while (v == seen);
                seen = v;
            }
            __syncthreads();   // tid0's acquire ordered before everyone's reads

            // ---- stage this slice's h quads; sync within the slice only ----
            {
                const float* hb = &g_h[t & 1][b0][0];
                if (ks < 3) {
                    for (int i = p; i < TB * 14; i += 128) {
                        int bl = i / 14, kq = kq_lo + (i - bl * 14);
                        float4 v = __ldcg(reinterpret_cast<const float4*>(
                                              hb + (size_t)bl * HDIM + 4 * kq));
                        *reinterpret_cast<float4*>(&s.hs[bl][4 * kq]) = v;
                    }
                } else {
                    int bl = p >> 3, kq = 42 + (p & 7);   // 128 items exactly
                    float4 v = __ldcg(reinterpret_cast<const float4*>(
                                          hb + (size_t)bl * HDIM + 4 * kq));
                    *reinterpret_cast<float4*>(&s.hs[bl][4 * kq]) = v;
                }
                bar_named128(8 + ks);
            }

            // ---- recurrent GEMM: fully unrolled, compile-time trip counts ----
            if (ks < 3) {
                #pragma unroll
                for (int i = 0; i < 14; ++i) GEMM_QUAD(s.whh, s.hs, kq_lo + i);
            } else {
                #pragma unroll
                for (int i = 0; i < 8; ++i) GEMM_QUAD(s.whh, s.hs, 42 + i);
            }
        }

        // ---- all 4 slices export partials (real rows only) ----
        if (act) {
            float (*rd)[RED_S] = s.red[ks];
            rd[r0g][bb]      = f2sum(A00); rd[r0g][bb + 4]  = f2sum(A01);
            rd[r0g][bb + 8]  = f2sum(A02); rd[r0g][bb + 12] = f2sum(A03);
            rd[r1g][bb]      = f2sum(A10); rd[r1g][bb + 4]  = f2sum(A11);
            rd[r1g][bb + 8]  = f2sum(A12); rd[r1g][bb + 12] = f2sum(A13);
            rd[r2g][bb]      = f2sum(A20); rd[r2g][bb + 4]  = f2sum(A21);
            rd[r2g][bb + 8]  = f2sum(A22); rd[r2g][bb + 12] = f2sum(A23);
            rd[r3g][bb]      = f2sum(A30); rd[r3g][bb + 4]  = f2sum(A31);
            rd[r3g][bb + 8]  = f2sum(A32); rd[r3g][bb + 12] = f2sum(A33);
        }
        __syncthreads();

        // ---- fused gather + activations + cell update: 1 item/thread ----
        const int nxt = (t + 1) & 1;
        if (c_act) {
            float vi = s.red[0][cu][cb]            + s.red[1][cu][cb]
                     + s.red[2][cu][cb]            + s.red[3][cu][cb]            + bsi;
            float vf = s.red[0][cu + TH][cb]       + s.red[1][cu + TH][cb]
                     + s.red[2][cu + TH][cb]       + s.red[3][cu + TH][cb]       + bsf;
            float vg = s.red[0][cu + 2*TH][cb]     + s.red[1][cu + 2*TH][cb]
                     + s.red[2][cu + 2*TH][cb]     + s.red[3][cu + 2*TH][cb]     + bsg;
            float vo = s.red[0][cu + 3*TH][cb]     + s.red[1][cu + 3*TH][cb]
                     + s.red[2][cu + 3*TH][cb]     + s.red[3][cu + 3*TH][cb]     + bso;
            float gi = sigf(vi), gf = sigf(vf);
            float gg = tanh_fast(vg), go = sigf(vo);
            creg = gf * creg + gi * gg;
            __stcg(&g_h[nxt][b0 + cb][hd0 + cu], go * tanh_fast(creg));
        }
        if (t + 1 < T_STEPS && xp_on)
            s.xs[nxt][xp_bl][xp_k] = xreg;

        __syncthreads();   // covers stcg (for arrive-release), xs STS, red reuse

        if (tid == 0) {
            // monotonic counter: every 8th arrival flips the epoch (no reset)
            unsigned old = atom_add_acqrel(cnt, 1u);
            if ((old & (GSIZE - 1u)) == GSIZE - 1u)
                atom_add_acqrel(ep, 1u);
        }

        // ---- x-part for t+1 (slice 3; hidden under peer skew) ----
        if (t + 1 < T_STEPS) do_xpart(nxt);
    }

    // ---- final wait: peers' h(2047) (stored in g_h[0]) visible ----
    if (tid == 0) {
        unsigned v;
        do { v = ld_acq(ep); } while (v == seen);
        seen = v;
    }
    __syncthreads();
    {
        const float4* hsrc = reinterpret_cast<const float4*>(&g_h[0][b0][0]);
        for (int i = tid; i < TB * (HDIM / 4); i += NTHREADS) {
            int bl = i / 50, kq = i - bl * 50;
            float4 v = __ldcg(hsrc + i);
            *reinterpret_cast<float4*>(&s.hs[bl][kq * 4]) = v;
        }
    }
    __syncthreads();

    // outputs: [out(512) | h(51200) | c(51200)]
    if (ht == 0 && out_size >= NCLS * BATCH) {
        if (tid < TB * NCLS) {
            int bl = tid >> 1, cls = tid & 1;
            float acc = fc_b[cls];
            #pragma unroll 4
            for (int k = 0; k < HDIM; ++k)
                acc += s.hs[bl][k] * fc_w[cls * HDIM + k];
            out[(b0 + bl) * NCLS + cls] = sigf(acc);
        }
    }
    if (ht == 0 && out_size >= NCLS * BATCH + BATCH * HDIM) {
        for (int i = tid; i < TB * HDIM; i += NTHREADS) {
            int bl = i / HDIM, k = i - bl * HDIM;
            out[NCLS * BATCH + (size_t)(b0 + bl) * HDIM + k] = s.hs[bl][k];
        }
    }
    if (out_size >= NCLS * BATCH + 2 * BATCH * HDIM) {
        if (c_act) {   // c lives in the owning thread's register
            out[NCLS * BATCH + BATCH * HDIM
                + (size_t)(b0 + cb) * HDIM + hd0 + cu] = creg;
        }
    }
}

extern "C" void kernel_launch(void* const* d_in, const int* in_sizes, int n_in,
                              void* d_out, int out_size) {
    const float* x     = (const float*)d_in[0];
    // d_in[1]=X_lengths (unused), d_in[2]=h0, d_in[3]=c0 (zeros, ignored)
    const float* W_ih  = (const float*)d_in[4];
    const float* W_hh  = (const float*)d_in[5];
    const float* b_ih  = (const float*)d_in[6];
    const float* b_hh  = (const float*)d_in[7];
    const float* fc_w  = (const float*)d_in[8];
    const float* fc_b  = (const float*)d_in[9];

    int smem = (int)sizeof(SmemLayout);
    cudaFuncSetAttribute(lstm_persistent,
                         cudaFuncAttributeMaxDynamicSharedMemorySize, smem);
    lstm_persistent<<<GRID_CTAS, NTHREADS, smem>>>(
        x, W_ih, W_hh, b_ih, b_hh, fc_w, fc_b, (float*)d_out, out_size);
}

// round 16
// speedup vs baseline: 1.0197x; 1.0197x over previous
#include <cuda_runtime.h>
#include <cstdint>

#define T_STEPS 2048
#define BATCH   256
#define HDIM    200
#define IN_DIM  27
#define NCLS    2

#define NGROUPS  16     // batch tiles; groups are mutually independent
#define GSIZE    8      // hd tiles per group -> 8-CTA barrier groups
#define GRID_CTAS (NGROUPS * GSIZE)   // 128 CTAs, 1/SM (SMEM-limited)
#define TB 16     // batches per CTA
#define TH 25     // hidden units per CTA
#define ROWS 100  // 4 gates * TH
#define ROWS_PAD 128
#define NTHREADS 512    // 16 warps; K split 4 ways; 4x4 register tile per thread

// SMEM strides (floats): 16B-aligned rows, conflict-free quad-banks for LDS.128
#define WHH_S 212   // 53 quads/row, 53%8=5 -> 8 consecutive rows hit 8 banks
#define WIH_S 36    // 9 quads,  9%8=1
#define HS_S  204   // 51 quads, 51%8=3
#define XS_S  36
#define RED_S 17    // odd stride -> low-conflict partial exchange

struct SmemLayout {
    float whh[ROWS_PAD][WHH_S];      // 108544 B
    float wih[ROWS_PAD][WIH_S];      //  18432 B
    float hs[TB][HS_S];              //  13056 B (h staging, full HDIM per batch)
    float xs[2][TB][XS_S];           //   4608 B (double-buffered x)
    float bias[ROWS_PAD];            //    512 B
    float red[3][ROWS_PAD][RED_S];   //  26112 B (K-split partials, slices 1..3)
};
// total 171264 B -> 1 CTA/SM; 128 CTAs <= 148 SMs -> all co-resident.

__device__ float g_h[2][BATCH][HDIM];          // double-buffered h exchange (L2)
__device__ unsigned g_cnt[NGROUPS * 64];       // per-group arrive counters (monotonic)
__device__ unsigned g_ep [NGROUPS * 64];       // per-group epochs, 256B apart

typedef unsigned long long u64;

__device__ __forceinline__ void ffma2(u64& d, u64 a, u64 b) {
    asm("fma.rn.f32x2 %0, %1, %2, %3;" : "=l"(d) : "l"(a), "l"(b), "l"(d));
}
__device__ __forceinline__ float f2sum(u64 v) {
    return __uint_as_float((unsigned)v) + __uint_as_float((unsigned)(v >> 32));
}
__device__ __forceinline__ float sigf(float x) {
    float e = __expf(-x);
    return __fdividef(1.0f, 1.0f + e);
}
__device__ __forceinline__ float tanh_fast(float x) {
    float e = __expf(-2.0f * x);
    return __fdividef(2.0f, 1.0f + e) - 1.0f;
}
__device__ __forceinline__ unsigned ld_acq(const unsigned* p) {
    unsigned v;
    asm volatile("ld.acquire.gpu.u32 %0, [%1];" : "=r"(v) : "l"(p) : "memory");
    return v;
}
__device__ __forceinline__ unsigned atom_add_acqrel(unsigned* p, unsigned v) {
    unsigned o;
    asm volatile("atom.add.acq_rel.gpu.u32 %0, [%1], %2;"
                 : "=r"(o) : "l"(p), "r"(v) : "memory");
    return o;
}
__device__ __forceinline__ void bar_named128(int id) {  // 128-thread named barrier
    asm volatile("bar.sync %0, 128;" :: "r"(id) : "memory");
}

__global__ void __launch_bounds__(NTHREADS, 1)
lstm_persistent(const float* __restrict__ x,      // [B][T][27]
                const float* __restrict__ W_ih,   // [800][27]
                const float* __restrict__ W_hh,   // [800][200]
                const float* __restrict__ b_ih,   // [800]
                const float* __restrict__ b_hh,   // [800]
                const float* __restrict__ fc_w,   // [2][200]
                const float* __restrict__ fc_b,   // [2]
                float* __restrict__ out, int out_size)
{
    extern __shared__ float smem_f[];
    SmemLayout& s = *reinterpret_cast<SmemLayout*>(smem_f);

    const int tid = threadIdx.x;
    const int bt  = blockIdx.x >> 3;   // group id (batch tile)
    const int ht  = blockIdx.x & 7;    // hd tile within group
    const int b0  = bt * TB;
    const int hd0 = ht * TH;

    unsigned* cnt = &g_cnt[bt * 64];
    unsigned* ep  = &g_ep [bt * 64];

    // ---- one-time staging: weight slices (row r = gate*25 + hl), bias ----
    for (int i = tid; i < ROWS_PAD * HDIM; i += NTHREADS) {
        int r = i / HDIM, k = i - r * HDIM;
        float v = 0.0f;
        if (r < ROWS) {
            int gate = r / TH, hl = r - gate * TH;
            v = W_hh[(gate * HDIM + hd0 + hl) * HDIM + k];
        }
        s.whh[r][k] = v;
    }
    for (int i = tid; i < ROWS_PAD * 28; i += NTHREADS) {
        int r = i / 28, k = i - r * 28;
        float v = 0.0f;
        if (r < ROWS && k < IN_DIM) {
            int gate = r / TH, hl = r - gate * TH;
            v = W_ih[(gate * HDIM + hd0 + hl) * IN_DIM + k];
        }
        s.wih[r][k] = v;
    }
    if (tid < ROWS_PAD) {
        float v = 0.0f;
        if (tid < ROWS) {
            int gate = tid / TH, hl = tid - gate * TH;
            int gr = gate * HDIM + hd0 + hl;
            v = b_ih[gr] + b_hh[gr];
        }
        s.bias[tid] = v;
    }
    for (int i = tid; i < TB * 28; i += NTHREADS) { // xs[0] for t=0
        int bl = i / 28, k = i - bl * 28;
        s.xs[0][bl][k] = (k < IN_DIM)
            ? x[((size_t)(b0 + bl) * T_STEPS + 0) * IN_DIM + k] : 0.0f;
    }

    // Barrier bookkeeping: read epoch BEFORE first arrive (race-free; relative
    // compare -> replay/wrap safe).
    unsigned seen = 0;
    unsigned i_flipped = 0;   // R16: flipper skips its own poll next wait
    if (tid == 0) seen = ld_acq(ep);
    __syncthreads();

    // K-split-4, gate-aligned tile: ks = slice; rows {jb, jb+25, jb+50, jb+75}
    // = gates {i,f,g,o} of hidden unit jb. Active rows only for jb < 25.
    const int ks = tid >> 7;          // 0..3
    const int p  = tid & 127;
    const int jb = p >> 2;            // 0..31 (25..31 = padding rows)
    const int bb = p & 3;
    const bool act = (jb < TH);       // owns real rows
    const int r0g = jb, r1g = jb + 25, r2g = jb + 50, r3g = jb + 75;
    // h-quad slices: ks0:[0,14) ks1:[14,28) ks2:[28,42) ks3:[42,50) (+x on ks3)
    const int kq_lo = 14 * ks;

    // ks0 caches bias (i,f,g,o of unit jb) and keeps c in registers
    float bsi = 0, bsf = 0, bsg = 0, bso = 0;
    float creg0 = 0, creg1 = 0, creg2 = 0, creg3 = 0;
    if (ks == 0 && act) {
        bsi = s.bias[r0g]; bsf = s.bias[r1g];
        bsg = s.bias[r2g]; bso = s.bias[r3g];
    }

    // x prefetch coordinates (tid < 448 holds one padded x element)
    const int xp_bl = tid / 28;
    const int xp_k  = tid - xp_bl * 28;
    const bool xp_on = (tid < TB * 28);

    // 4x4 accumulator tile [gate][batch]
    u64 A00, A01, A02, A03, A10, A11, A12, A13;
    u64 A20, A21, A22, A23, A30, A31, A32, A33;

#define GEMM_QUAD(WARR, VARR, Q)                                               \
    {                                                                          \
        ulonglong2 W0 = *reinterpret_cast<const ulonglong2*>(&WARR[r0g][4*(Q)]);\
        ulonglong2 W1 = *reinterpret_cast<const ulonglong2*>(&WARR[r1g][4*(Q)]);\
        ulonglong2 W2 = *reinterpret_cast<const ulonglong2*>(&WARR[r2g][4*(Q)]);\
        ulonglong2 W3 = *reinterpret_cast<const ulonglong2*>(&WARR[r3g][4*(Q)]);\
        ulonglong2 V0 = *reinterpret_cast<const ulonglong2*>(&VARR[bb][4*(Q)]);\
        ulonglong2 V1 = *reinterpret_cast<const ulonglong2*>(&VARR[bb+4][4*(Q)]);\
        ulonglong2 V2 = *reinterpret_cast<const ulonglong2*>(&VARR[bb+8][4*(Q)]);\
        ulonglong2 V3 = *reinterpret_cast<const ulonglong2*>(&VARR[bb+12][4*(Q)]);\
        ffma2(A00,V0.x,W0.x); ffma2(A00,V0.y,W0.y);                            \
        ffma2(A01,V1.x,W0.x); ffma2(A01,V1.y,W0.y);                            \
        ffma2(A02,V2.x,W0.x); ffma2(A02,V2.y,W0.y);                            \
        ffma2(A03,V3.x,W0.x); ffma2(A03,V3.y,W0.y);                            \
        ffma2(A10,V0.x,W1.x); ffma2(A10,V0.y,W1.y);                            \
        ffma2(A11,V1.x,W1.x); ffma2(A11,V1.y,W1.y);                            \
        ffma2(A12,V2.x,W1.x); ffma2(A12,V2.y,W1.y);                            \
        ffma2(A13,V3.x,W1.x); ffma2(A13,V3.y,W1.y);                            \
        ffma2(A20,V0.x,W2.x); ffma2(A20,V0.y,W2.y);                            \
        ffma2(A21,V1.x,W2.x); ffma2(A21,V1.y,W2.y);                            \
        ffma2(A22,V2.x,W2.x); ffma2(A22,V2.y,W2.y);                            \
        ffma2(A23,V3.x,W2.x); ffma2(A23,V3.y,W2.y);                            \
        ffma2(A30,V0.x,W3.x); ffma2(A30,V0.y,W3.y);                            \
        ffma2(A31,V1.x,W3.x); ffma2(A31,V1.y,W3.y);                            \
        ffma2(A32,V2.x,W3.x); ffma2(A32,V2.y,W3.y);                            \
        ffma2(A33,V3.x,W3.x); ffma2(A33,V3.y,W3.y);                            \
    }

    // reset accumulators + (slice 3 only) x-part for buffer `buf`
    auto do_xpart = [&](int buf) {
        A00=A01=A02=A03=A10=A11=A12=A13=0ull;
        A20=A21=A22=A23=A30=A31=A32=A33=0ull;
        if (ks == 3) {
            #pragma unroll
            for (int q = 0; q < 7; ++q) GEMM_QUAD(s.wih, s.xs[buf], q);
        }
    };

    do_xpart(0);   // x-part for t=0 (xs[0] staged above, synced)

    for (int t = 0; t < T_STEPS; ++t) {
        // prefetch x(t+1): DRAM latency overlaps wait + staging + GEMM
        float xreg = 0.0f;
        if (t + 1 < T_STEPS && xp_on && xp_k < IN_DIM)
            xreg = __ldg(&x[((size_t)(b0 + xp_bl) * T_STEPS + (t + 1)) * IN_DIM + xp_k]);

        if (t > 0) {
            // ---- wait for peers' h(t-1) ----
            // R16: if this CTA performed the flip, its cnt-arrive already
            // acquired all peers' released stores; skip the L2 poll entirely.
            if (tid == 0) {
                if (i_flipped) {
                    seen += 1;
                    i_flipped = 0;
                } else {
                    unsigned v;
                    do { v = ld_acq(ep); } while (v == seen);
                    seen = v;
                }
            }
            __syncthreads();   // tid0's acquire ordered before everyone's reads

            // ---- stage this slice's h quads; sync within the slice only ----
            {
                const float* hb = &g_h[t & 1][b0][0];
                if (ks < 3) {
                    for (int i = p; i < TB * 14; i += 128) {
                        int bl = i / 14, kq = kq_lo + (i - bl * 14);
                        float4 v = __ldcg(reinterpret_cast<const float4*>(
                                              hb + (size_t)bl * HDIM + 4 * kq));
                        *reinterpret_cast<float4*>(&s.hs[bl][4 * kq]) = v;
                    }
                } else {
                    int bl = p >> 3, kq = 42 + (p & 7);   // 128 items exactly
                    float4 v = __ldcg(reinterpret_cast<const float4*>(
                                          hb + (size_t)bl * HDIM + 4 * kq));
                    *reinterpret_cast<float4*>(&s.hs[bl][4 * kq]) = v;
                }
                bar_named128(8 + ks);
            }

            // ---- recurrent GEMM: fully unrolled, compile-time trip counts ----
            if (ks < 3) {
                #pragma unroll
                for (int i = 0; i < 14; ++i) GEMM_QUAD(s.whh, s.hs, kq_lo + i);
            } else {
                #pragma unroll
                for (int i = 0; i < 8; ++i) GEMM_QUAD(s.whh, s.hs, 42 + i);
            }
        }

        // ---- K-split-4 reduction: slices 1..3 export (real rows only) ----
        if (ks != 0 && act) {
            float (*rd)[RED_S] = s.red[ks - 1];
            rd[r0g][bb]      = f2sum(A00); rd[r0g][bb + 4]  = f2sum(A01);
            rd[r0g][bb + 8]  = f2sum(A02); rd[r0g][bb + 12] = f2sum(A03);
            rd[r1g][bb]      = f2sum(A10); rd[r1g][bb + 4]  = f2sum(A11);
            rd[r1g][bb + 8]  = f2sum(A12); rd[r1g][bb + 12] = f2sum(A13);
            rd[r2g][bb]      = f2sum(A20); rd[r2g][bb + 4]  = f2sum(A21);
            rd[r2g][bb + 8]  = f2sum(A22); rd[r2g][bb + 12] = f2sum(A23);
            rd[r3g][bb]      = f2sum(A30); rd[r3g][bb + 4]  = f2sum(A31);
            rd[r3g][bb + 8]  = f2sum(A32); rd[r3g][bb + 12] = f2sum(A33);
        }
        __syncthreads();

        // ---- fused gather + activations + cell update (ks0, register c) ----
        const int nxt = (t + 1) & 1;
        if (ks == 0 && act) {
            #define CELL(N, AI, AF, AG, AO, CREG)                              \
            {                                                                  \
                int b = bb + 4 * (N);                                          \
                float vi = f2sum(AI) + s.red[0][r0g][b] + s.red[1][r0g][b]     \
                         + s.red[2][r0g][b] + bsi;                             \
                float vf = f2sum(AF) + s.red[0][r1g][b] + s.red[1][r1g][b]     \
                         + s.red[2][r1g][b] + bsf;                             \
                float vg = f2sum(AG) + s.red[0][r2g][b] + s.red[1][r2g][b]     \
                         + s.red[2][r2g][b] + bsg;                             \
                float vo = f2sum(AO) + s.red[0][r3g][b] + s.red[1][r3g][b]     \
                         + s.red[2][r3g][b] + bso;                             \
                float gi = sigf(vi), gf = sigf(vf);                            \
                float gg = tanh_fast(vg), go = sigf(vo);                       \
                CREG = gf * CREG + gi * gg;                                    \
                __stcg(&g_h[nxt][b0 + b][hd0 + jb], go * tanh_fast(CREG));     \
            }
            CELL(0, A00, A10, A20, A30, creg0)
            CELL(1, A01, A11, A21, A31, creg1)
            CELL(2, A02, A12, A22, A32, creg2)
            CELL(3, A03, A13, A23, A33, creg3)
            #undef CELL
        }
        if (t + 1 < T_STEPS && xp_on)
            s.xs[nxt][xp_bl][xp_k] = xreg;

        __syncthreads();   // covers stcg (for arrive-release), xs STS, red reuse

        if (tid == 0) {
            // R16: monotonic counter; flip on every 8th arrival; remember it.
            unsigned old = atom_add_acqrel(cnt, 1u);
            if ((old & (GSIZE - 1u)) == GSIZE - 1u) {
                atom_add_acqrel(ep, 1u);      // flip
                i_flipped = 1;
            }
        }

        // ---- x-part for t+1 (slice 3; hidden under peer skew) ----
        if (t + 1 < T_STEPS) do_xpart(nxt);
    }

    // ---- final wait: peers' h(2047) (stored in g_h[0]) visible ----
    if (tid == 0) {
        if (i_flipped) {
            seen += 1;
            i_flipped = 0;
        } else {
            unsigned v;
            do { v = ld_acq(ep); } while (v == seen);
            seen = v;
        }
    }
    __syncthreads();
    {
        const float4* hsrc = reinterpret_cast<const float4*>(&g_h[0][b0][0]);
        for (int i = tid; i < TB * (HDIM / 4); i += NTHREADS) {
            int bl = i / 50, kq = i - bl * 50;
            float4 v = __ldcg(hsrc + i);
            *reinterpret_cast<float4*>(&s.hs[bl][kq * 4]) = v;
        }
    }
    __syncthreads();

    // outputs: [out(512) | h(51200) | c(51200)]
    if (ht == 0 && out_size >= NCLS * BATCH) {
        if (tid < TB * NCLS) {
            int bl = tid >> 1, cls = tid & 1;
            float acc = fc_b[cls];
            #pragma unroll 4
            for (int k = 0; k < HDIM; ++k)
                acc += s.hs[bl][k] * fc_w[cls * HDIM + k];
            out[(b0 + bl) * NCLS + cls] = sigf(acc);
        }
    }
    if (ht == 0 && out_size >= NCLS * BATCH + BATCH * HDIM) {
        for (int i = tid; i < TB * HDIM; i += NTHREADS) {
            int bl = i / HDIM, k = i - bl * HDIM;
            out[NCLS * BATCH + (size_t)(b0 + bl) * HDIM + k] = s.hs[bl][k];
        }
    }
    if (out_size >= NCLS * BATCH + 2 * BATCH * HDIM) {
        if (ks == 0 && act) {   // c lives in ks0 registers
            #pragma unroll
            for (int n = 0; n < 4; ++n) {
                int b = bb + 4 * n;
                float cv = (n == 0) ? creg0 : (n == 1) ? creg1
                                            : (n == 2) ? creg2 : creg3;
                out[NCLS * BATCH + BATCH * HDIM
                    + (size_t)(b0 + b) * HDIM + hd0 + jb] = cv;
            }
        }
    }
}

extern "C" void kernel_launch(void* const* d_in, const int* in_sizes, int n_in,
                              void* d_out, int out_size) {
    const float* x     = (const float*)d_in[0];
    // d_in[1]=X_lengths (unused), d_in[2]=h0, d_in[3]=c0 (zeros, ignored)
    const float* W_ih  = (const float*)d_in[4];
    const float* W_hh  = (const float*)d_in[5];
    const float* b_ih  = (const float*)d_in[6];
    const float* b_hh  = (const float*)d_in[7];
    const float* fc_w  = (const float*)d_in[8];
    const float* fc_b  = (const float*)d_in[9];

    int smem = (int)sizeof(SmemLayout);
    cudaFuncSetAttribute(lstm_persistent,
                         cudaFuncAttributeMaxDynamicSharedMemorySize, smem);
    lstm_persistent<<<GRID_CTAS, NTHREADS, smem>>>(
        x, W_ih, W_hh, b_ih, b_hh, fc_w, fc_b, (float*)d_out, out_size);
}